// round 10
// baseline (speedup 1.0000x reference)
#include <cuda_runtime.h>
#include <cuda_bf16.h>
#include <cstdint>
#include <cstddef>

// Problem constants
#define PB 2
#define PS 2048
#define PD 1536
#define PH 12
#define PDH 128
#define PFFN 8960
#define PLENC 512
#define PBS (PB*PS)       // 4096 rows
#define PBSE (PB*PLENC)   // 1024 rows

// ---------------------------------------------------------------------------
// Scratch (__device__ globals; allocation-free)
// ---------------------------------------------------------------------------
__device__ float g_mods[PB*6*2*PD];
__device__ float g_x   [(size_t)PBS*PD];
__device__ float g_q   [(size_t)PBS*PD];
__device__ float g_k   [(size_t)PBS*PD];
__device__ float g_v   [(size_t)PBS*PD];
__device__ float g_attn[(size_t)PBS*PD];
__device__ float g_tmp [(size_t)PBS*PD];
__device__ float g_k2  [(size_t)PBSE*PD];
__device__ float g_v2  [(size_t)PBSE*PD];
__device__ float g_ffn [(size_t)PBS*PFFN];

// ---------------------------------------------------------------------------
// mods[b][j][t][d] = scale_shift_table[j][d] + temb[b][j][t][d]
// ---------------------------------------------------------------------------
__global__ void build_mods_kernel(const float* __restrict__ sst,
                                  const float* __restrict__ temb,
                                  float* __restrict__ mods)
{
    int i = blockIdx.x * 256 + threadIdx.x;
    const int total = PB*6*2*PD;
    if (i >= total) return;
    int d = i % PD;
    int j = (i / (2*PD)) % 6;
    mods[i] = sst[j*PD + d] + temb[i];
}

// ---------------------------------------------------------------------------
// LayerNorm + AdaLN modulation: out = LN(in) * (1 + scale_tok) + shift_tok
// One block (256 thr) per row of 1536.
// ---------------------------------------------------------------------------
__global__ void __launch_bounds__(256) ln_mod_kernel(
    const float* __restrict__ in, const float* __restrict__ mods,
    const int* __restrict__ segp, float* __restrict__ out,
    int jscale, int jshift)
{
    const int row = blockIdx.x;        // b*S + s
    const int b = row / PS, s = row % PS;
    const int tid = threadIdx.x;
    const int lane = tid & 31, wid = tid >> 5;

    const float* x = in + (size_t)row * PD;
    float v[6];
    float sum = 0.f;
#pragma unroll
    for (int m = 0; m < 6; m++) { v[m] = x[tid + m*256]; sum += v[m]; }

    __shared__ float red[8];
    __shared__ float sbc[2];
#pragma unroll
    for (int o = 16; o > 0; o >>= 1) sum += __shfl_xor_sync(0xffffffffu, sum, o);
    if (lane == 0) red[wid] = sum;
    __syncthreads();
    if (tid == 0) {
        float t = 0.f;
#pragma unroll
        for (int i = 0; i < 8; i++) t += red[i];
        sbc[0] = t * (1.f / PD);
    }
    __syncthreads();
    const float mu = sbc[0];
    float sq = 0.f;
#pragma unroll
    for (int m = 0; m < 6; m++) { float dd = v[m] - mu; sq += dd*dd; }
#pragma unroll
    for (int o = 16; o > 0; o >>= 1) sq += __shfl_xor_sync(0xffffffffu, sq, o);
    if (lane == 0) red[wid] = sq;
    __syncthreads();
    if (tid == 0) {
        float t = 0.f;
#pragma unroll
        for (int i = 0; i < 8; i++) t += red[i];
        sbc[1] = t * (1.f / PD);
    }
    __syncthreads();
    const float inv = rsqrtf(sbc[1] + 1e-6f);

    int seg = *segp; seg = min(max(0, seg), PS);
    const int t = (s >= seg) ? 1 : 0;
    const float* sc = mods + (((size_t)b*6 + jscale)*2 + t)*PD;
    const float* sh = mods + (((size_t)b*6 + jshift)*2 + t)*PD;
    float* o = out + (size_t)row * PD;
#pragma unroll
    for (int m = 0; m < 6; m++) {
        int d = tid + m*256;
        o[d] = (v[m] - mu) * inv * (1.f + sc[d]) + sh[d];
    }
}

// ---------------------------------------------------------------------------
// out = base + t * gate_tok   (jgate < 0 => plain residual add)
// ---------------------------------------------------------------------------
__global__ void addmod_kernel(const float* __restrict__ base,
                              const float* __restrict__ t,
                              const float* __restrict__ mods,
                              const int* __restrict__ segp,
                              float* __restrict__ out, int jgate)
{
    int i = blockIdx.x * 256 + threadIdx.x;
    if (i >= PBS*PD) return;
    float g = 1.f;
    if (jgate >= 0) {
        int d = i % PD;
        int s = (i / PD) % PS;
        int b = i / (PD*PS);
        int seg = *segp; seg = min(max(0, seg), PS);
        int tt = (s >= seg) ? 1 : 0;
        g = mods[(((size_t)b*6 + jgate)*2 + tt)*PD + d];
    }
    out[i] = base[i] + t[i] * g;
}

// ---------------------------------------------------------------------------
// RoPE (interleaved pairs, per-head, cos/sin per (b,s,i)) on q and k in place
// ---------------------------------------------------------------------------
__global__ void rope_kernel(float* __restrict__ q, float* __restrict__ k,
                            const float* __restrict__ cosb,
                            const float* __restrict__ sinb)
{
    int i = blockIdx.x * 256 + threadIdx.x;
    const int NP = PB*PS*PH*(PDH/2);
    if (i >= NP) return;
    int p  = i % 64;
    int h  = (i / 64) % PH;
    int bs = i / (64*PH);
    float c  = cosb[(size_t)bs*64 + p];
    float sn = sinb[(size_t)bs*64 + p];
    size_t e = ((size_t)bs*PH + h)*PDH + 2*p;
    float xr = q[e], xi = q[e+1];
    q[e]   = xr*c - xi*sn;
    q[e+1] = xr*sn + xi*c;
    xr = k[e]; xi = k[e+1];
    k[e]   = xr*c - xi*sn;
    k[e+1] = xr*sn + xi*c;
}

// ---------------------------------------------------------------------------
// SGEMM: C[M,N] = A[M,K] @ B[K,N] (+bias) (+gelu). 128x128x8 tile, 256 thr.
// M,N % 128 == 0, K % 8 == 0, K,N % 4 == 0 assumed.
// ---------------------------------------------------------------------------
__device__ __forceinline__ float gelu_tanh(float x) {
    float x3 = x*x*x;
    return 0.5f*x*(1.f + tanhf(0.7978845608028654f*(x + 0.044715f*x3)));
}

__global__ void __launch_bounds__(256) sgemm_kernel(
    const float* __restrict__ A, const float* __restrict__ B,
    const float* __restrict__ bias, float* __restrict__ C,
    int M, int N, int K, int act)
{
    __shared__ float As[8][128];
    __shared__ float Bs[8][128];
    const int tid = threadIdx.x;
    const int bm = blockIdx.y, bn = blockIdx.x;
    const int arow = tid >> 1, acol = (tid & 1) << 2;
    const int brow = tid >> 5, bcol = (tid & 31) << 2;
    const int tx = tid & 15, ty = tid >> 4;
    const float* Ab = A + (size_t)bm * 128 * K;
    const float* Bb = B + (size_t)bn * 128;

    float acc[8][8];
#pragma unroll
    for (int i = 0; i < 8; i++)
#pragma unroll
        for (int j = 0; j < 8; j++) acc[i][j] = 0.f;

    for (int k0 = 0; k0 < K; k0 += 8) {
        float4 av = *reinterpret_cast<const float4*>(Ab + (size_t)arow*K + k0 + acol);
        As[acol+0][arow] = av.x; As[acol+1][arow] = av.y;
        As[acol+2][arow] = av.z; As[acol+3][arow] = av.w;
        *reinterpret_cast<float4*>(&Bs[brow][bcol]) =
            *reinterpret_cast<const float4*>(Bb + (size_t)(k0 + brow)*N + bcol);
        __syncthreads();
#pragma unroll
        for (int kk = 0; kk < 8; kk++) {
            float4 a0 = *reinterpret_cast<const float4*>(&As[kk][ty*8]);
            float4 a1 = *reinterpret_cast<const float4*>(&As[kk][ty*8+4]);
            float4 b0 = *reinterpret_cast<const float4*>(&Bs[kk][tx*8]);
            float4 b1 = *reinterpret_cast<const float4*>(&Bs[kk][tx*8+4]);
            float ar[8] = {a0.x,a0.y,a0.z,a0.w,a1.x,a1.y,a1.z,a1.w};
            float br[8] = {b0.x,b0.y,b0.z,b0.w,b1.x,b1.y,b1.z,b1.w};
#pragma unroll
            for (int i = 0; i < 8; i++)
#pragma unroll
                for (int j = 0; j < 8; j++) acc[i][j] += ar[i]*br[j];
        }
        __syncthreads();
    }

#pragma unroll
    for (int i = 0; i < 8; i++) {
        size_t row = (size_t)bm*128 + ty*8 + i;
#pragma unroll
        for (int j = 0; j < 8; j += 4) {
            int col = bn*128 + tx*8 + j;
            float4 r;
            r.x = acc[i][j+0]; r.y = acc[i][j+1]; r.z = acc[i][j+2]; r.w = acc[i][j+3];
            if (bias) { r.x += bias[col+0]; r.y += bias[col+1]; r.z += bias[col+2]; r.w += bias[col+3]; }
            if (act == 1) { r.x = gelu_tanh(r.x); r.y = gelu_tanh(r.y); r.z = gelu_tanh(r.z); r.w = gelu_tanh(r.w); }
            *reinterpret_cast<float4*>(C + row*N + col) = r;
        }
    }
}

// ---------------------------------------------------------------------------
// Flash attention fp32. Layouts: Q,O: (b, s, h, dh) contiguous; K,V same with
// kv length Skv. Br=Bc=64, DH=128, 256 threads, online softmax.
// ---------------------------------------------------------------------------
#define FBR 64
#define FBC 64
#define QPAD 129
#define KPAD 129
#define VPAD 132
#define SPAD 65
#define FLASH_SMEM_BYTES ((FBR*QPAD + FBC*KPAD + FBC*VPAD + FBR*SPAD + 3*FBR) * 4)

__global__ void __launch_bounds__(256) flash_kernel(
    const float* __restrict__ Q, const float* __restrict__ Kp,
    const float* __restrict__ Vp, float* __restrict__ O,
    int Sq, int Skv)
{
    extern __shared__ float sm[];
    float* sQ = sm;
    float* sK = sQ + FBR*QPAD;
    float* sV = sK + FBC*KPAD;
    float* sS = sV + FBC*VPAD;
    float* sM = sS + FBR*SPAD;
    float* sL = sM + FBR;
    float* sA = sL + FBR;

    const int qt = blockIdx.x, h = blockIdx.y, b = blockIdx.z;
    const int tid = threadIdx.x;
    const int rs = PH * PDH;  // 1536

    const float* Qb = Q  + ((size_t)(b*Sq + qt*FBR) * PH + h) * PDH;
    const float* Kb = Kp + ((size_t)(b*Skv)          * PH + h) * PDH;
    const float* Vb = Vp + ((size_t)(b*Skv)          * PH + h) * PDH;

    for (int i = tid*4; i < FBR*PDH; i += 1024) {
        int r = i >> 7, c = i & 127;
        float4 v = *reinterpret_cast<const float4*>(Qb + (size_t)r*rs + c);
        float* dst = sQ + r*QPAD + c;
        dst[0]=v.x; dst[1]=v.y; dst[2]=v.z; dst[3]=v.w;
    }
    if (tid < FBR) { sM[tid] = -3e38f; sL[tid] = 0.f; }

    float acc[32];
#pragma unroll
    for (int i = 0; i < 32; i++) acc[i] = 0.f;

    const int orow = tid >> 2;
    const int cb   = (tid & 3) << 2;
    const int ty = tid >> 4, tx = tid & 15;
    const float scale = 0.08838834764831845f;  // 1/sqrt(128)

    for (int kt = 0; kt < Skv; kt += FBC) {
        __syncthreads();  // protect sK/sV/sS from previous iteration readers
        for (int i = tid*4; i < FBC*PDH; i += 1024) {
            int r = i >> 7, c = i & 127;
            float4 kv = *reinterpret_cast<const float4*>(Kb + (size_t)(kt+r)*rs + c);
            float* kd = sK + r*KPAD + c;
            kd[0]=kv.x; kd[1]=kv.y; kd[2]=kv.z; kd[3]=kv.w;
            float4 vv = *reinterpret_cast<const float4*>(Vb + (size_t)(kt+r)*rs + c);
            *reinterpret_cast<float4*>(sV + r*VPAD + c) = vv;
        }
        __syncthreads();

        // S = Q K^T (64x64), 16x16 threads x 4x4 microtile
        float s4[4][4];
#pragma unroll
        for (int i = 0; i < 4; i++)
#pragma unroll
            for (int j = 0; j < 4; j++) s4[i][j] = 0.f;
        for (int d = 0; d < PDH; d++) {
            float a0 = sQ[(ty*4+0)*QPAD + d];
            float a1 = sQ[(ty*4+1)*QPAD + d];
            float a2 = sQ[(ty*4+2)*QPAD + d];
            float a3 = sQ[(ty*4+3)*QPAD + d];
            float b0 = sK[(tx*4+0)*KPAD + d];
            float b1 = sK[(tx*4+1)*KPAD + d];
            float b2 = sK[(tx*4+2)*KPAD + d];
            float b3 = sK[(tx*4+3)*KPAD + d];
            s4[0][0]+=a0*b0; s4[0][1]+=a0*b1; s4[0][2]+=a0*b2; s4[0][3]+=a0*b3;
            s4[1][0]+=a1*b0; s4[1][1]+=a1*b1; s4[1][2]+=a1*b2; s4[1][3]+=a1*b3;
            s4[2][0]+=a2*b0; s4[2][1]+=a2*b1; s4[2][2]+=a2*b2; s4[2][3]+=a2*b3;
            s4[3][0]+=a3*b0; s4[3][1]+=a3*b1; s4[3][2]+=a3*b2; s4[3][3]+=a3*b3;
        }
#pragma unroll
        for (int i = 0; i < 4; i++)
#pragma unroll
            for (int j = 0; j < 4; j++)
                sS[(ty*4+i)*SPAD + tx*4+j] = s4[i][j]*scale;
        __syncthreads();

        // online softmax stats: 4 threads per row
        {
            int r = tid >> 2, part = tid & 3;
            float* srow = sS + r*SPAD + part*16;
            float mloc = srow[0];
#pragma unroll
            for (int c = 1; c < 16; c++) mloc = fmaxf(mloc, srow[c]);
            mloc = fmaxf(mloc, __shfl_xor_sync(0xffffffffu, mloc, 1));
            mloc = fmaxf(mloc, __shfl_xor_sync(0xffffffffu, mloc, 2));
            float mold = sM[r];
            float mnew = fmaxf(mold, mloc);
            float suml = 0.f;
#pragma unroll
            for (int c = 0; c < 16; c++) {
                float p = __expf(srow[c] - mnew);
                srow[c] = p;
                suml += p;
            }
            suml += __shfl_xor_sync(0xffffffffu, suml, 1);
            suml += __shfl_xor_sync(0xffffffffu, suml, 2);
            if (part == 0) {
                float alpha = __expf(mold - mnew);
                sM[r] = mnew;
                sL[r] = sL[r]*alpha + suml;
                sA[r] = alpha;
            }
        }
        __syncthreads();

        // O += P V : each thread: one row, 32 cols at (tid&3)*4 + 16*m + ii
        float alpha = sA[orow];
#pragma unroll
        for (int i = 0; i < 32; i++) acc[i] *= alpha;
        const float* prow = sS + orow*SPAD;
        for (int kk = 0; kk < FBC; kk++) {
            float p = prow[kk];
            const float* vr = sV + kk*VPAD + cb;
#pragma unroll
            for (int m = 0; m < 8; m++) {
                float4 vv = *reinterpret_cast<const float4*>(vr + 16*m);
                acc[m*4+0] += p*vv.x; acc[m*4+1] += p*vv.y;
                acc[m*4+2] += p*vv.z; acc[m*4+3] += p*vv.w;
            }
        }
    }

    float linv = 1.f / sL[orow];
    float* Ob = O + ((size_t)(b*Sq + qt*FBR + orow)*PH + h)*PDH + cb;
#pragma unroll
    for (int m = 0; m < 8; m++) {
        float4 o4;
        o4.x = acc[m*4+0]*linv; o4.y = acc[m*4+1]*linv;
        o4.z = acc[m*4+2]*linv; o4.w = acc[m*4+3]*linv;
        *reinterpret_cast<float4*>(Ob + 16*m) = o4;
    }
}

// ---------------------------------------------------------------------------
// Host launch
// ---------------------------------------------------------------------------
static void run_sgemm(const float* A, const float* B, const float* bias,
                      float* C, int M, int N, int K, int act)
{
    dim3 grid(N/128, M/128);
    sgemm_kernel<<<grid, 256>>>(A, B, bias, C, M, N, K, act);
}

extern "C" void kernel_launch(void* const* d_in, const int* in_sizes, int n_in,
                              void* d_out, int out_size)
{
    // locate seg_idx (unique size-1 input); all other tensors keep their order
    int sidx = -1;
    for (int i = 0; i < n_in; i++) if (in_sizes[i] == 1) { sidx = i; break; }
    if (sidx < 0) sidx = 5;  // dict-order fallback

    const float* p[20];
    int j = 0;
    for (int i = 0; i < n_in && j < 20; i++) {
        if (i == sidx) continue;
        p[j++] = (const float*)d_in[i];
    }
    const float* hidden = p[0];
    const float* enc    = p[1];
    const float* temb   = p[2];
    const float* rcos   = p[3];
    const float* rsin   = p[4];
    const float* Wq1 = p[5],  *Wk1 = p[6],  *Wv1 = p[7],  *Wo1 = p[8];
    const float* bo1 = p[9];
    const float* Wq2 = p[10], *Wk2 = p[11], *Wv2 = p[12], *Wo2 = p[13];
    const float* bo2 = p[14];
    const float* Wf1 = p[15], *bf1 = p[16], *Wf2 = p[17], *bf2 = p[18];
    const float* sst = p[19];
    const int* seg = (const int*)d_in[sidx];
    float* out = (float*)d_out;

    void *vp;
    cudaGetSymbolAddress(&vp, g_mods); float* mods = (float*)vp;
    cudaGetSymbolAddress(&vp, g_x);    float* xb   = (float*)vp;
    cudaGetSymbolAddress(&vp, g_q);    float* qb   = (float*)vp;
    cudaGetSymbolAddress(&vp, g_k);    float* kb   = (float*)vp;
    cudaGetSymbolAddress(&vp, g_v);    float* vb   = (float*)vp;
    cudaGetSymbolAddress(&vp, g_attn); float* ab   = (float*)vp;
    cudaGetSymbolAddress(&vp, g_tmp);  float* tb   = (float*)vp;
    cudaGetSymbolAddress(&vp, g_k2);   float* k2b  = (float*)vp;
    cudaGetSymbolAddress(&vp, g_v2);   float* v2b  = (float*)vp;
    cudaGetSymbolAddress(&vp, g_ffn);  float* fb   = (float*)vp;

    cudaFuncSetAttribute(flash_kernel,
        cudaFuncAttributeMaxDynamicSharedMemorySize, FLASH_SMEM_BYTES);

    // 1. modulation table
    build_mods_kernel<<<(PB*6*2*PD + 255)/256, 256>>>(sst, temb, mods);

    // 2. norm1 + modulation  -> x
    ln_mod_kernel<<<PBS, 256>>>(hidden, mods, seg, xb, /*scale*/1, /*shift*/0);

    // 3. self-attn QKV
    run_sgemm(xb, Wq1, nullptr, qb, PBS, PD, PD, 0);
    run_sgemm(xb, Wk1, nullptr, kb, PBS, PD, PD, 0);
    run_sgemm(xb, Wv1, nullptr, vb, PBS, PD, PD, 0);

    // 4. RoPE on q, k
    rope_kernel<<<(PB*PS*PH*64 + 255)/256, 256>>>(qb, kb, rcos, rsin);

    // 5. self attention
    flash_kernel<<<dim3(PS/FBR, PH, PB), 256, FLASH_SMEM_BYTES>>>(
        qb, kb, vb, ab, PS, PS);

    // 6. O-proj + gated residual: out = hidden + (attn@Wo1 + bo1) * gate
    run_sgemm(ab, Wo1, bo1, tb, PBS, PD, PD, 0);
    addmod_kernel<<<(PBS*PD)/256, 256>>>(hidden, tb, mods, seg, out, /*gate*/2);

    // 7. cross attention (q from un-normalized hidden, per reference)
    run_sgemm(out, Wq2, nullptr, qb, PBS, PD, PD, 0);
    run_sgemm(enc, Wk2, nullptr, k2b, PBSE, PD, PD, 0);
    run_sgemm(enc, Wv2, nullptr, v2b, PBSE, PD, PD, 0);
    flash_kernel<<<dim3(PS/FBR, PH, PB), 256, FLASH_SMEM_BYTES>>>(
        qb, k2b, v2b, ab, PS, PLENC);
    run_sgemm(ab, Wo2, bo2, tb, PBS, PD, PD, 0);
    addmod_kernel<<<(PBS*PD)/256, 256>>>(out, tb, mods, seg, out, /*plain*/-1);

    // 8. FFN: norm3 + c-mod -> gelu(y@Wf1+bf1) @ Wf2 + bf2, gated residual
    ln_mod_kernel<<<PBS, 256>>>(out, mods, seg, xb, /*c_scale*/4, /*c_shift*/3);
    run_sgemm(xb, Wf1, bf1, fb, PBS, PFFN, PD, /*gelu*/1);
    run_sgemm(fb, Wf2, bf2, tb, PBS, PD, PFFN, 0);
    addmod_kernel<<<(PBS*PD)/256, 256>>>(out, tb, mods, seg, out, /*c_gate*/5);
}

// round 16
// speedup vs baseline: 1.8275x; 1.8275x over previous
#include <cuda_runtime.h>
#include <cuda_bf16.h>
#include <cstdint>
#include <cstddef>

// Problem constants
#define PB 2
#define PS 2048
#define PD 1536
#define PH 12
#define PDH 128
#define PFFN 8960
#define PLENC 512
#define PBS (PB*PS)       // 4096 rows
#define PBSE (PB*PLENC)   // 1024 rows

#define DDSZ (PD*PD)
#define WF1SZ (PD*PFFN)
#define WPOOL (8*DDSZ + 2*WF1SZ)

// ---------------------------------------------------------------------------
// Scratch (__device__ globals; allocation-free)
// ---------------------------------------------------------------------------
__device__ float g_mods[PB*6*2*PD];
__device__ float g_x   [(size_t)PBS*PD];
__device__ float g_q   [(size_t)PBS*PD];
__device__ float g_k   [(size_t)PBS*PD];
__device__ float g_v   [(size_t)PBS*PD];
__device__ float g_attn[(size_t)PBS*PD];
__device__ float g_tmp [(size_t)PBS*PD];
__device__ float g_k2  [(size_t)PBSE*PD];
__device__ float g_v2  [(size_t)PBSE*PD];
__device__ float g_ffn [(size_t)PBS*PFFN];
__device__ __nv_bfloat16 g_wth[WPOOL];
__device__ __nv_bfloat16 g_wtl[WPOOL];
__device__ __nv_bfloat16 g_ah [(size_t)PBS*PFFN];
__device__ __nv_bfloat16 g_al [(size_t)PBS*PFFN];

// ---------------------------------------------------------------------------
// Baseline-PTX helpers (sm_80+: cp.async, ldmatrix, mma.sync — no 'a' features)
// ---------------------------------------------------------------------------
__device__ __forceinline__ uint32_t smem_u32(const void* p) {
    uint32_t a;
    asm("{ .reg .u64 t; cvta.to.shared.u64 t, %1; cvt.u32.u64 %0, t; }" : "=r"(a) : "l"(p));
    return a;
}
__device__ __forceinline__ void cp_async16(uint32_t saddr, const void* g) {
    asm volatile("cp.async.cg.shared.global [%0], [%1], 16;" :: "r"(saddr), "l"(g) : "memory");
}
#define CP_COMMIT() asm volatile("cp.async.commit_group;" ::: "memory")
#define CP_WAIT(n)  asm volatile("cp.async.wait_group %0;" :: "n"(n) : "memory")

__device__ __forceinline__ void ldsm_x4(uint32_t (&r)[4], uint32_t addr) {
    asm volatile("ldmatrix.sync.aligned.m8n8.x4.shared.b16 {%0,%1,%2,%3}, [%4];"
        : "=r"(r[0]), "=r"(r[1]), "=r"(r[2]), "=r"(r[3]) : "r"(addr));
}
__device__ __forceinline__ void mma16816(float* d, const uint32_t* a, const uint32_t* b) {
    asm volatile("mma.sync.aligned.m16n8k16.row.col.f32.bf16.bf16.f32 "
        "{%0,%1,%2,%3}, {%4,%5,%6,%7}, {%8,%9}, {%0,%1,%2,%3};"
        : "+f"(d[0]), "+f"(d[1]), "+f"(d[2]), "+f"(d[3])
        : "r"(a[0]), "r"(a[1]), "r"(a[2]), "r"(a[3]), "r"(b[0]), "r"(b[1]));
}

// ---------------------------------------------------------------------------
// mods[b][j][t][d] = scale_shift_table[j][d] + temb[b][j][t][d]
// ---------------------------------------------------------------------------
__global__ void build_mods_kernel(const float* __restrict__ sst,
                                  const float* __restrict__ temb,
                                  float* __restrict__ mods)
{
    int i = blockIdx.x * 256 + threadIdx.x;
    const int total = PB*6*2*PD;
    if (i >= total) return;
    int d = i % PD;
    int j = (i / (2*PD)) % 6;
    mods[i] = sst[j*PD + d] + temb[i];
}

// ---------------------------------------------------------------------------
// LayerNorm + AdaLN modulation
// ---------------------------------------------------------------------------
__global__ void __launch_bounds__(256) ln_mod_kernel(
    const float* __restrict__ in, const float* __restrict__ mods,
    const int* __restrict__ segp, float* __restrict__ out,
    int jscale, int jshift)
{
    const int row = blockIdx.x;
    const int b = row / PS, s = row % PS;
    const int tid = threadIdx.x;
    const int lane = tid & 31, wid = tid >> 5;

    const float* x = in + (size_t)row * PD;
    float v[6];
    float sum = 0.f;
#pragma unroll
    for (int m = 0; m < 6; m++) { v[m] = x[tid + m*256]; sum += v[m]; }

    __shared__ float red[8];
    __shared__ float sbc[2];
#pragma unroll
    for (int o = 16; o > 0; o >>= 1) sum += __shfl_xor_sync(0xffffffffu, sum, o);
    if (lane == 0) red[wid] = sum;
    __syncthreads();
    if (tid == 0) {
        float t = 0.f;
#pragma unroll
        for (int i = 0; i < 8; i++) t += red[i];
        sbc[0] = t * (1.f / PD);
    }
    __syncthreads();
    const float mu = sbc[0];
    float sq = 0.f;
#pragma unroll
    for (int m = 0; m < 6; m++) { float dd = v[m] - mu; sq += dd*dd; }
#pragma unroll
    for (int o = 16; o > 0; o >>= 1) sq += __shfl_xor_sync(0xffffffffu, sq, o);
    if (lane == 0) red[wid] = sq;
    __syncthreads();
    if (tid == 0) {
        float t = 0.f;
#pragma unroll
        for (int i = 0; i < 8; i++) t += red[i];
        sbc[1] = t * (1.f / PD);
    }
    __syncthreads();
    const float inv = rsqrtf(sbc[1] + 1e-6f);

    int seg = *segp; seg = min(max(0, seg), PS);
    const int t = (s >= seg) ? 1 : 0;
    const float* sc = mods + (((size_t)b*6 + jscale)*2 + t)*PD;
    const float* sh = mods + (((size_t)b*6 + jshift)*2 + t)*PD;
    float* o = out + (size_t)row * PD;
#pragma unroll
    for (int m = 0; m < 6; m++) {
        int d = tid + m*256;
        o[d] = (v[m] - mu) * inv * (1.f + sc[d]) + sh[d];
    }
}

// ---------------------------------------------------------------------------
// out = base + t * gate_tok   (jgate < 0 => plain residual add)
// ---------------------------------------------------------------------------
__global__ void addmod_kernel(const float* __restrict__ base,
                              const float* __restrict__ t,
                              const float* __restrict__ mods,
                              const int* __restrict__ segp,
                              float* __restrict__ out, int jgate)
{
    int i = blockIdx.x * 256 + threadIdx.x;
    if (i >= PBS*PD) return;
    float g = 1.f;
    if (jgate >= 0) {
        int d = i % PD;
        int s = (i / PD) % PS;
        int b = i / (PD*PS);
        int seg = *segp; seg = min(max(0, seg), PS);
        int tt = (s >= seg) ? 1 : 0;
        g = mods[(((size_t)b*6 + jgate)*2 + tt)*PD + d];
    }
    out[i] = base[i] + t[i] * g;
}

// ---------------------------------------------------------------------------
// RoPE (interleaved pairs) on q and k in place
// ---------------------------------------------------------------------------
__global__ void rope_kernel(float* __restrict__ q, float* __restrict__ k,
                            const float* __restrict__ cosb,
                            const float* __restrict__ sinb)
{
    int i = blockIdx.x * 256 + threadIdx.x;
    const int NP = PB*PS*PH*(PDH/2);
    if (i >= NP) return;
    int p  = i % 64;
    int h  = (i / 64) % PH;
    int bs = i / (64*PH);
    float c  = cosb[(size_t)bs*64 + p];
    float sn = sinb[(size_t)bs*64 + p];
    size_t e = ((size_t)bs*PH + h)*PDH + 2*p;
    float xr = q[e], xi = q[e+1];
    q[e]   = xr*c - xi*sn;
    q[e+1] = xr*sn + xi*c;
    xr = k[e]; xi = k[e+1];
    k[e]   = xr*c - xi*sn;
    k[e+1] = xr*sn + xi*c;
}

// ---------------------------------------------------------------------------
// fp32 -> bf16 hi/lo split (elementwise)
// ---------------------------------------------------------------------------
__global__ void split_kernel(const float* __restrict__ src,
                             __nv_bfloat16* __restrict__ hi,
                             __nv_bfloat16* __restrict__ lo, int n)
{
    int i = blockIdx.x * 256 + threadIdx.x;
    if (i >= n) return;
    float x = src[i];
    __nv_bfloat16 h = __float2bfloat16(x);
    hi[i] = h;
    lo[i] = __float2bfloat16(x - __bfloat162float(h));
}

// ---------------------------------------------------------------------------
// W [R,C] fp32 -> W^T [C,R] bf16 hi/lo
// ---------------------------------------------------------------------------
__global__ void transpose_split_kernel(const float* __restrict__ src,
                                       __nv_bfloat16* __restrict__ hi,
                                       __nv_bfloat16* __restrict__ lo,
                                       int R, int C)
{
    __shared__ float t[32][33];
    int c0 = blockIdx.x*32, r0 = blockIdx.y*32;
    int tx = threadIdx.x, ty = threadIdx.y;   // 32 x 8
#pragma unroll
    for (int i = 0; i < 32; i += 8)
        t[ty+i][tx] = src[(size_t)(r0+ty+i)*C + c0+tx];
    __syncthreads();
#pragma unroll
    for (int i = 0; i < 32; i += 8) {
        float x = t[tx][ty+i];
        size_t o = (size_t)(c0+ty+i)*R + r0+tx;
        __nv_bfloat16 h = __float2bfloat16(x);
        hi[o] = h;
        lo[o] = __float2bfloat16(x - __bfloat162float(h));
    }
}

// ---------------------------------------------------------------------------
// Split-bf16 GEMM via mma.sync (baseline PTX): C[M,N] = A[M,K] @ B^T
//   A hi/lo [M,K] bf16 row-major; B hi/lo [N,K] bf16 row-major.
//   3 MMAs per fragment pair: Ah*Bh + Ah*Bl + Al*Bh (fp32 accumulate).
// BM=128 BN=128 BK=32, 256 thr = 8 warps (2M x 4N), warp tile 64x32,
// cp.async double-buffered smem [128][40] per matrix (pad -> conflict-free
// ldmatrix), fused bias/gelu epilogue.
// ---------------------------------------------------------------------------
__device__ __forceinline__ float gelu_tanh(float x) {
    float x3 = x*x*x;
    return 0.5f*x*(1.f + tanhf(0.7978845608028654f*(x + 0.044715f*x3)));
}

#define TCPAD 40
#define MAT_BYTES (128*TCPAD*2)            // 10240
#define TC_STAGE_BYTES (4*MAT_BYTES)       // 40960: Ah|Al|Bh|Bl
#define TC_SMEM_TOTAL (2*TC_STAGE_BYTES)   // 81920

__global__ void __launch_bounds__(256) tc_gemm_kernel(
    const __nv_bfloat16* __restrict__ Ah, const __nv_bfloat16* __restrict__ Al,
    const __nv_bfloat16* __restrict__ Bh, const __nv_bfloat16* __restrict__ Bl,
    const float* __restrict__ bias, float* __restrict__ C,
    int M, int N, int K, int act)
{
    extern __shared__ char tcsm[];
    const uint32_t smb = smem_u32(tcsm);
    const int tid = threadIdx.x;
    const int wid = tid >> 5, lane = tid & 31;
    const int mw = wid >> 2;          // 0..1 (M side, 64 rows each)
    const int nw = wid & 3;           // 0..3 (N side, 32 cols each)
    const int bm = blockIdx.y, bn = blockIdx.x;

    const size_t arow0 = (size_t)bm * 128;
    const size_t brow0 = (size_t)bn * 128;
    const __nv_bfloat16* gsrc0 = Ah + arow0*K;
    const __nv_bfloat16* gsrc1 = Al + arow0*K;
    const __nv_bfloat16* gsrc2 = Bh + brow0*K;
    const __nv_bfloat16* gsrc3 = Bl + brow0*K;

    auto load_stage = [&](int kc, int s) {
        uint32_t sb = smb + s*TC_STAGE_BYTES;
#pragma unroll
        for (int j = 0; j < 2; j++) {
            int idx = tid + j*256;          // 0..511
            int row = idx >> 2;
            int ch  = idx & 3;              // 4 x 16B = 64B = 32 bf16
            uint32_t soff = (uint32_t)(row*(TCPAD*2) + ch*16);
            size_t goff = (size_t)row*K + kc + ch*8;
            cp_async16(sb + 0*MAT_BYTES + soff, gsrc0 + goff);
            cp_async16(sb + 1*MAT_BYTES + soff, gsrc1 + goff);
            cp_async16(sb + 2*MAT_BYTES + soff, gsrc2 + goff);
            cp_async16(sb + 3*MAT_BYTES + soff, gsrc3 + goff);
        }
        CP_COMMIT();
    };

    float acc[4][4][4];
#pragma unroll
    for (int i = 0; i < 4; i++)
#pragma unroll
        for (int j = 0; j < 4; j++)
#pragma unroll
            for (int r = 0; r < 4; r++) acc[i][j][r] = 0.f;

    const int nk = K / 32;
    load_stage(0, 0);
    load_stage(32, 1);

    const uint32_t lrow = lane & 15;
    const uint32_t lhalf = (lane >> 4) * 8;   // 0 or 8 (elements)

    for (int i = 0; i < nk; i++) {
        int s = i & 1;
        if (i + 1 < nk) CP_WAIT(1); else CP_WAIT(0);
        __syncthreads();
        uint32_t sb = smb + s*TC_STAGE_BYTES;
#pragma unroll
        for (int ks = 0; ks < 2; ks++) {
            const uint32_t kb = ks*16;
            uint32_t ah4[4][4], al4[4][4];
#pragma unroll
            for (int mt = 0; mt < 4; mt++) {
                uint32_t off = ((mw*64 + mt*16 + lrow)*TCPAD + kb + lhalf)*2;
                ldsm_x4(ah4[mt], sb + 0*MAT_BYTES + off);
                ldsm_x4(al4[mt], sb + 1*MAT_BYTES + off);
            }
            uint32_t bh2[4][2], bl2[4][2];
#pragma unroll
            for (int g = 0; g < 2; g++) {
                uint32_t off = ((nw*32 + g*16 + lrow)*TCPAD + kb + lhalf)*2;
                uint32_t r[4];
                ldsm_x4(r, sb + 2*MAT_BYTES + off);
                bh2[g*2+0][0] = r[0]; bh2[g*2+0][1] = r[2];
                bh2[g*2+1][0] = r[1]; bh2[g*2+1][1] = r[3];
                ldsm_x4(r, sb + 3*MAT_BYTES + off);
                bl2[g*2+0][0] = r[0]; bl2[g*2+0][1] = r[2];
                bl2[g*2+1][0] = r[1]; bl2[g*2+1][1] = r[3];
            }
#pragma unroll
            for (int mt = 0; mt < 4; mt++)
#pragma unroll
                for (int nt = 0; nt < 4; nt++) {
                    mma16816(acc[mt][nt], ah4[mt], bh2[nt]);
                    mma16816(acc[mt][nt], ah4[mt], bl2[nt]);
                    mma16816(acc[mt][nt], al4[mt], bh2[nt]);
                }
        }
        __syncthreads();
        if (i + 2 < nk) load_stage((i + 2) * 32, s);
    }

    // Epilogue: fragment layout m16n8: c0,c1 at (lane/4, (lane%4)*2 + {0,1});
    // c2,c3 at (+8 rows). Fused bias/gelu, float2 stores.
    const int r0 = bm*128 + mw*64 + (lane >> 2);
    const int c0 = bn*128 + nw*32 + (lane & 3)*2;
#pragma unroll
    for (int mt = 0; mt < 4; mt++) {
#pragma unroll
        for (int nt = 0; nt < 4; nt++) {
            int rr = r0 + mt*16;
            int cc = c0 + nt*8;
            float v0 = acc[mt][nt][0], v1 = acc[mt][nt][1];
            float v2 = acc[mt][nt][2], v3 = acc[mt][nt][3];
            if (bias) {
                float b0 = bias[cc], b1 = bias[cc+1];
                v0 += b0; v1 += b1; v2 += b0; v3 += b1;
            }
            if (act) {
                v0 = gelu_tanh(v0); v1 = gelu_tanh(v1);
                v2 = gelu_tanh(v2); v3 = gelu_tanh(v3);
            }
            float2 p0 = {v0, v1}, p1 = {v2, v3};
            *reinterpret_cast<float2*>(C + (size_t)rr*N + cc) = p0;
            *reinterpret_cast<float2*>(C + (size_t)(rr+8)*N + cc) = p1;
        }
    }
}

// ---------------------------------------------------------------------------
// Flash attention fp32 (unchanged from validated R10 kernel)
// ---------------------------------------------------------------------------
#define FBR 64
#define FBC 64
#define QPAD 129
#define KPAD 129
#define VPAD 132
#define SPAD 65
#define FLASH_SMEM_BYTES ((FBR*QPAD + FBC*KPAD + FBC*VPAD + FBR*SPAD + 3*FBR) * 4)

__global__ void __launch_bounds__(256) flash_kernel(
    const float* __restrict__ Q, const float* __restrict__ Kp,
    const float* __restrict__ Vp, float* __restrict__ O,
    int Sq, int Skv)
{
    extern __shared__ float sm[];
    float* sQ = sm;
    float* sK = sQ + FBR*QPAD;
    float* sV = sK + FBC*KPAD;
    float* sS = sV + FBC*VPAD;
    float* sM = sS + FBR*SPAD;
    float* sL = sM + FBR;
    float* sA = sL + FBR;

    const int qt = blockIdx.x, h = blockIdx.y, b = blockIdx.z;
    const int tid = threadIdx.x;
    const int rs = PH * PDH;

    const float* Qb = Q  + ((size_t)(b*Sq + qt*FBR) * PH + h) * PDH;
    const float* Kb = Kp + ((size_t)(b*Skv)          * PH + h) * PDH;
    const float* Vb = Vp + ((size_t)(b*Skv)          * PH + h) * PDH;

    for (int i = tid*4; i < FBR*PDH; i += 1024) {
        int r = i >> 7, c = i & 127;
        float4 v = *reinterpret_cast<const float4*>(Qb + (size_t)r*rs + c);
        float* dst = sQ + r*QPAD + c;
        dst[0]=v.x; dst[1]=v.y; dst[2]=v.z; dst[3]=v.w;
    }
    if (tid < FBR) { sM[tid] = -3e38f; sL[tid] = 0.f; }

    float acc[32];
#pragma unroll
    for (int i = 0; i < 32; i++) acc[i] = 0.f;

    const int orow = tid >> 2;
    const int cb   = (tid & 3) << 2;
    const int ty = tid >> 4, tx = tid & 15;
    const float scale = 0.08838834764831845f;

    for (int kt = 0; kt < Skv; kt += FBC) {
        __syncthreads();
        for (int i = tid*4; i < FBC*PDH; i += 1024) {
            int r = i >> 7, c = i & 127;
            float4 kv = *reinterpret_cast<const float4*>(Kb + (size_t)(kt+r)*rs + c);
            float* kd = sK + r*KPAD + c;
            kd[0]=kv.x; kd[1]=kv.y; kd[2]=kv.z; kd[3]=kv.w;
            float4 vv = *reinterpret_cast<const float4*>(Vb + (size_t)(kt+r)*rs + c);
            *reinterpret_cast<float4*>(sV + r*VPAD + c) = vv;
        }
        __syncthreads();

        float s4[4][4];
#pragma unroll
        for (int i = 0; i < 4; i++)
#pragma unroll
            for (int j = 0; j < 4; j++) s4[i][j] = 0.f;
        for (int d = 0; d < PDH; d++) {
            float a0 = sQ[(ty*4+0)*QPAD + d];
            float a1 = sQ[(ty*4+1)*QPAD + d];
            float a2 = sQ[(ty*4+2)*QPAD + d];
            float a3 = sQ[(ty*4+3)*QPAD + d];
            float b0 = sK[(tx*4+0)*KPAD + d];
            float b1 = sK[(tx*4+1)*KPAD + d];
            float b2 = sK[(tx*4+2)*KPAD + d];
            float b3 = sK[(tx*4+3)*KPAD + d];
            s4[0][0]+=a0*b0; s4[0][1]+=a0*b1; s4[0][2]+=a0*b2; s4[0][3]+=a0*b3;
            s4[1][0]+=a1*b0; s4[1][1]+=a1*b1; s4[1][2]+=a1*b2; s4[1][3]+=a1*b3;
            s4[2][0]+=a2*b0; s4[2][1]+=a2*b1; s4[2][2]+=a2*b2; s4[2][3]+=a2*b3;
            s4[3][0]+=a3*b0; s4[3][1]+=a3*b1; s4[3][2]+=a3*b2; s4[3][3]+=a3*b3;
        }
#pragma unroll
        for (int i = 0; i < 4; i++)
#pragma unroll
            for (int j = 0; j < 4; j++)
                sS[(ty*4+i)*SPAD + tx*4+j] = s4[i][j]*scale;
        __syncthreads();

        {
            int r = tid >> 2, part = tid & 3;
            float* srow = sS + r*SPAD + part*16;
            float mloc = srow[0];
#pragma unroll
            for (int c = 1; c < 16; c++) mloc = fmaxf(mloc, srow[c]);
            mloc = fmaxf(mloc, __shfl_xor_sync(0xffffffffu, mloc, 1));
            mloc = fmaxf(mloc, __shfl_xor_sync(0xffffffffu, mloc, 2));
            float mold = sM[r];
            float mnew = fmaxf(mold, mloc);
            float suml = 0.f;
#pragma unroll
            for (int c = 0; c < 16; c++) {
                float p = __expf(srow[c] - mnew);
                srow[c] = p;
                suml += p;
            }
            suml += __shfl_xor_sync(0xffffffffu, suml, 1);
            suml += __shfl_xor_sync(0xffffffffu, suml, 2);
            if (part == 0) {
                float alpha = __expf(mold - mnew);
                sM[r] = mnew;
                sL[r] = sL[r]*alpha + suml;
                sA[r] = alpha;
            }
        }
        __syncthreads();

        float alpha = sA[orow];
#pragma unroll
        for (int i = 0; i < 32; i++) acc[i] *= alpha;
        const float* prow = sS + orow*SPAD;
        for (int kk = 0; kk < FBC; kk++) {
            float p = prow[kk];
            const float* vr = sV + kk*VPAD + cb;
#pragma unroll
            for (int m = 0; m < 8; m++) {
                float4 vv = *reinterpret_cast<const float4*>(vr + 16*m);
                acc[m*4+0] += p*vv.x; acc[m*4+1] += p*vv.y;
                acc[m*4+2] += p*vv.z; acc[m*4+3] += p*vv.w;
            }
        }
    }

    float linv = 1.f / sL[orow];
    float* Ob = O + ((size_t)(b*Sq + qt*FBR + orow)*PH + h)*PDH + cb;
#pragma unroll
    for (int m = 0; m < 8; m++) {
        float4 o4;
        o4.x = acc[m*4+0]*linv; o4.y = acc[m*4+1]*linv;
        o4.z = acc[m*4+2]*linv; o4.w = acc[m*4+3]*linv;
        *reinterpret_cast<float4*>(Ob + 16*m) = o4;
    }
}

// ---------------------------------------------------------------------------
// Host launch
// ---------------------------------------------------------------------------
static void run_tc(const __nv_bfloat16* ah, const __nv_bfloat16* al,
                   const __nv_bfloat16* bh, const __nv_bfloat16* bl,
                   const float* bias, float* C, int M, int N, int K, int act)
{
    dim3 grid(N/128, M/128);
    tc_gemm_kernel<<<grid, 256, TC_SMEM_TOTAL>>>(ah, al, bh, bl, bias, C, M, N, K, act);
}

extern "C" void kernel_launch(void* const* d_in, const int* in_sizes, int n_in,
                              void* d_out, int out_size)
{
    int sidx = -1;
    for (int i = 0; i < n_in; i++) if (in_sizes[i] == 1) { sidx = i; break; }
    if (sidx < 0) sidx = 5;

    const float* p[20];
    int j = 0;
    for (int i = 0; i < n_in && j < 20; i++) {
        if (i == sidx) continue;
        p[j++] = (const float*)d_in[i];
    }
    const float* hidden = p[0];
    const float* enc    = p[1];
    const float* temb   = p[2];
    const float* rcos   = p[3];
    const float* rsin   = p[4];
    const float* Wq1 = p[5],  *Wk1 = p[6],  *Wv1 = p[7],  *Wo1 = p[8];
    const float* bo1 = p[9];
    const float* Wq2 = p[10], *Wk2 = p[11], *Wv2 = p[12], *Wo2 = p[13];
    const float* bo2 = p[14];
    const float* Wf1 = p[15], *bf1 = p[16], *Wf2 = p[17], *bf2 = p[18];
    const float* sst = p[19];
    const int* seg = (const int*)d_in[sidx];
    float* out = (float*)d_out;

    void *vp;
    cudaGetSymbolAddress(&vp, g_mods); float* mods = (float*)vp;
    cudaGetSymbolAddress(&vp, g_x);    float* xb   = (float*)vp;
    cudaGetSymbolAddress(&vp, g_q);    float* qb   = (float*)vp;
    cudaGetSymbolAddress(&vp, g_k);    float* kb   = (float*)vp;
    cudaGetSymbolAddress(&vp, g_v);    float* vb   = (float*)vp;
    cudaGetSymbolAddress(&vp, g_attn); float* ab   = (float*)vp;
    cudaGetSymbolAddress(&vp, g_tmp);  float* tb   = (float*)vp;
    cudaGetSymbolAddress(&vp, g_k2);   float* k2b  = (float*)vp;
    cudaGetSymbolAddress(&vp, g_v2);   float* v2b  = (float*)vp;
    cudaGetSymbolAddress(&vp, g_ffn);  float* fb   = (float*)vp;
    cudaGetSymbolAddress(&vp, g_wth);  __nv_bfloat16* wth = (__nv_bfloat16*)vp;
    cudaGetSymbolAddress(&vp, g_wtl);  __nv_bfloat16* wtl = (__nv_bfloat16*)vp;
    cudaGetSymbolAddress(&vp, g_ah);   __nv_bfloat16* ah  = (__nv_bfloat16*)vp;
    cudaGetSymbolAddress(&vp, g_al);   __nv_bfloat16* al  = (__nv_bfloat16*)vp;

    cudaFuncSetAttribute(flash_kernel,
        cudaFuncAttributeMaxDynamicSharedMemorySize, FLASH_SMEM_BYTES);
    cudaFuncSetAttribute(tc_gemm_kernel,
        cudaFuncAttributeMaxDynamicSharedMemorySize, TC_SMEM_TOTAL);

    // 0. transpose+split all weights to [N,K] bf16 hi/lo
    const size_t oq1=0, ok1=DDSZ, ov1=2*(size_t)DDSZ, oo1=3*(size_t)DDSZ,
                 oq2=4*(size_t)DDSZ, ok2=5*(size_t)DDSZ, ov2=6*(size_t)DDSZ, oo2=7*(size_t)DDSZ,
                 of1=8*(size_t)DDSZ, of2=8*(size_t)DDSZ + WF1SZ;
    dim3 tsb(32, 8);
    transpose_split_kernel<<<dim3(PD/32, PD/32), tsb>>>(Wq1, wth+oq1, wtl+oq1, PD, PD);
    transpose_split_kernel<<<dim3(PD/32, PD/32), tsb>>>(Wk1, wth+ok1, wtl+ok1, PD, PD);
    transpose_split_kernel<<<dim3(PD/32, PD/32), tsb>>>(Wv1, wth+ov1, wtl+ov1, PD, PD);
    transpose_split_kernel<<<dim3(PD/32, PD/32), tsb>>>(Wo1, wth+oo1, wtl+oo1, PD, PD);
    transpose_split_kernel<<<dim3(PD/32, PD/32), tsb>>>(Wq2, wth+oq2, wtl+oq2, PD, PD);
    transpose_split_kernel<<<dim3(PD/32, PD/32), tsb>>>(Wk2, wth+ok2, wtl+ok2, PD, PD);
    transpose_split_kernel<<<dim3(PD/32, PD/32), tsb>>>(Wv2, wth+ov2, wtl+ov2, PD, PD);
    transpose_split_kernel<<<dim3(PD/32, PD/32), tsb>>>(Wo2, wth+oo2, wtl+oo2, PD, PD);
    transpose_split_kernel<<<dim3(PFFN/32, PD/32), tsb>>>(Wf1, wth+of1, wtl+of1, PD, PFFN);
    transpose_split_kernel<<<dim3(PD/32, PFFN/32), tsb>>>(Wf2, wth+of2, wtl+of2, PFFN, PD);

    // 1. modulation table + norm1
    build_mods_kernel<<<(PB*6*2*PD + 255)/256, 256>>>(sst, temb, mods);
    ln_mod_kernel<<<PBS, 256>>>(hidden, mods, seg, xb, 1, 0);

    // 2. self-attn QKV (split-bf16 tensor GEMMs)
    split_kernel<<<(PBS*PD + 255)/256, 256>>>(xb, ah, al, PBS*PD);
    run_tc(ah, al, wth+oq1, wtl+oq1, nullptr, qb, PBS, PD, PD, 0);
    run_tc(ah, al, wth+ok1, wtl+ok1, nullptr, kb, PBS, PD, PD, 0);
    run_tc(ah, al, wth+ov1, wtl+ov1, nullptr, vb, PBS, PD, PD, 0);

    rope_kernel<<<(PB*PS*PH*64 + 255)/256, 256>>>(qb, kb, rcos, rsin);
    flash_kernel<<<dim3(PS/FBR, PH, PB), 256, FLASH_SMEM_BYTES>>>(qb, kb, vb, ab, PS, PS);

    // 3. O-proj + gated residual
    split_kernel<<<(PBS*PD + 255)/256, 256>>>(ab, ah, al, PBS*PD);
    run_tc(ah, al, wth+oo1, wtl+oo1, bo1, tb, PBS, PD, PD, 0);
    addmod_kernel<<<(PBS*PD)/256, 256>>>(hidden, tb, mods, seg, out, 2);

    // 4. cross attention (q from un-normalized hidden, per reference)
    split_kernel<<<(PBS*PD + 255)/256, 256>>>(out, ah, al, PBS*PD);
    run_tc(ah, al, wth+oq2, wtl+oq2, nullptr, qb, PBS, PD, PD, 0);
    split_kernel<<<(PBSE*PD + 255)/256, 256>>>(enc, ah, al, PBSE*PD);
    run_tc(ah, al, wth+ok2, wtl+ok2, nullptr, k2b, PBSE, PD, PD, 0);
    run_tc(ah, al, wth+ov2, wtl+ov2, nullptr, v2b, PBSE, PD, PD, 0);
    flash_kernel<<<dim3(PS/FBR, PH, PB), 256, FLASH_SMEM_BYTES>>>(qb, k2b, v2b, ab, PS, PLENC);
    split_kernel<<<(PBS*PD + 255)/256, 256>>>(ab, ah, al, PBS*PD);
    run_tc(ah, al, wth+oo2, wtl+oo2, bo2, tb, PBS, PD, PD, 0);
    addmod_kernel<<<(PBS*PD)/256, 256>>>(out, tb, mods, seg, out, -1);

    // 5. FFN
    ln_mod_kernel<<<PBS, 256>>>(out, mods, seg, xb, 4, 3);
    split_kernel<<<(PBS*PD + 255)/256, 256>>>(xb, ah, al, PBS*PD);
    run_tc(ah, al, wth+of1, wtl+of1, bf1, fb, PBS, PFFN, PD, 1);
    split_kernel<<<(PBS*PFFN + 255)/256, 256>>>(fb, ah, al, PBS*PFFN);
    run_tc(ah, al, wth+of2, wtl+of2, bf2, tb, PBS, PD, PFFN, 0);
    addmod_kernel<<<(PBS*PD)/256, 256>>>(out, tb, mods, seg, out, 5);
}